// round 1
// baseline (speedup 1.0000x reference)
#include <cuda_runtime.h>
#include <cuda_bf16.h>

#define TT 256
#define MM 16
#define HH 256
#define II 128
#define NROW (MM*HH)          // 4096
#define NB 148                // persistent CTAs (<= SM count, all resident)
#define NTHR 256
#define NWARPS (NB*(NTHR/32)) // 1184

#define DT_ 0.042f
#define GAMMA_ 2.7f
#define EPS_ 4.7f

// ---- persistent scratch (no cudaMalloc allowed) ----
__device__ float    g_B[TT*NROW];     // precomputed W_in@u + bias, 4 MB
__device__ float    g_hy[2][NROW];    // double-buffered hy state
__device__ float    g_hz[NROW];
__device__ unsigned g_bar;            // grid barrier counter (memset to 0 each launch)

// ============================================================
// Precompute B[t, m*H+h] = mask[m] * dot(W_in[m,h,:], x[t,:]) + bias[m,h]
// grid = (T, M), block = 256 (one thread per h)
// ============================================================
__global__ void bin_kernel(const float* __restrict__ x,
                           const float* __restrict__ input_mask,
                           const float* __restrict__ W_in,
                           const float* __restrict__ bias) {
    __shared__ float4 xs[II/4];
    int t = blockIdx.x, m = blockIdx.y, h = threadIdx.x;
    if (h < II/4) xs[h] = ((const float4*)(x + (size_t)t*II))[h];
    __syncthreads();
    const float4* w4 = (const float4*)(W_in + ((size_t)m*HH + h)*II);
    float s = 0.f;
#pragma unroll
    for (int k = 0; k < II/4; ++k) {
        float4 a = w4[k], b = xs[k];
        s += a.x*b.x + a.y*b.y + a.z*b.z + a.w*b.w;
    }
    g_B[((size_t)t*MM + m)*HH + h] = input_mask[m]*s + bias[m*HH + h];
}

// ============================================================
// Persistent recurrent step kernel. One warp per output row (i,h).
// Skips wm blocks where conn[i,o]==0 (halves weight traffic).
// ============================================================
__global__ void __launch_bounds__(NTHR, 1)
step_kernel(const float* __restrict__ wm,
            const float* __restrict__ conn,
            const float* __restrict__ wrec,
            float* __restrict__ out) {
    __shared__ float hy_sh[NROW];        // 16 KB snapshot of hy
    __shared__ float conn_sh[MM*MM];
    __shared__ float scal_sh[MM];

    int tid  = threadIdx.x;
    int lane = tid & 31;
    int gwarp = blockIdx.x * (NTHR/32) + (tid >> 5);

    if (tid < MM*MM) conn_sh[tid] = conn[tid];
    __syncthreads();
    if (tid < MM) {
        float s = 0.f;
#pragma unroll
        for (int o = 0; o < MM; ++o) s += conn_sh[tid*MM + o];
        scal_sh[tid] = 1.f / fmaxf(s, 1.f);
    }

    float* state_out = out;                       // [T][M][2][H]
    float* fb_out    = out + (size_t)TT*MM*2*HH;  // [T][M][H]

    for (int t = 0; t < TT; ++t) {
        int p = t & 1;
        __syncthreads();   // protect hy_sh reuse + scal_sh first use
        {
            const float4* src = (const float4*)g_hy[p];
            float4* dst = (float4*)hy_sh;
            for (int k = tid; k < NROW/4; k += NTHR) dst[k] = src[k];
        }
        __syncthreads();

        const float4* hy4 = (const float4*)hy_sh;
        for (int row = gwarp; row < NROW; row += NWARPS) {
            int i = row >> 8, h = row & (HH-1);
            // ---- feedback: sum over nonzero conn blocks ----
            float fb = 0.f;
            const float* wmrow = wm + (((size_t)i*MM)*HH + h)*HH;  // wm[i][0][h][0]
#pragma unroll
            for (int o = 0; o < MM; ++o) {
                if (conn_sh[i*MM + o] != 0.f) {
                    const float4* w4 = (const float4*)(wmrow + (size_t)o*HH*HH);
                    const float4* b4 = hy4 + o*(HH/4);
                    float4 a = w4[lane],    b = b4[lane];
                    fb += a.x*b.x + a.y*b.y + a.z*b.z + a.w*b.w;
                    a = w4[lane+32]; b = b4[lane+32];
                    fb += a.x*b.x + a.y*b.y + a.z*b.z + a.w*b.w;
                }
            }
            // ---- block-diagonal recurrent term ----
            float rec = 0.f;
            {
                const float4* w4 = (const float4*)(wrec + ((size_t)i*HH + h)*HH);
                const float4* b4 = hy4 + i*(HH/4);
                float4 a = w4[lane],    b = b4[lane];
                rec += a.x*b.x + a.y*b.y + a.z*b.z + a.w*b.w;
                a = w4[lane+32]; b = b4[lane+32];
                rec += a.x*b.x + a.y*b.y + a.z*b.z + a.w*b.w;
            }
#pragma unroll
            for (int off = 16; off; off >>= 1) {
                fb  += __shfl_xor_sync(0xffffffffu, fb,  off);
                rec += __shfl_xor_sync(0xffffffffu, rec, off);
            }
            if (lane == 0) {
                fb *= scal_sh[i];
                float hyp = hy_sh[row];
                float hzp = g_hz[row];
                float pre = fb + rec + g_B[(size_t)t*NROW + row];
                float hzn = hzp + DT_ * (tanhf(pre) - GAMMA_*hyp - EPS_*hzp);
                float hyn = hyp + DT_ * hzn;
                g_hz[row]        = hzn;
                g_hy[1-p][row]   = hyn;
                size_t sb = ((size_t)(t*MM + i)*2)*HH;
                state_out[sb + h]        = hyn;
                state_out[sb + HH + h]   = hzn;
                fb_out[(size_t)(t*MM + i)*HH + h] = fb;
            }
        }

        // ---- grid barrier (skip after last step) ----
        if (t == TT-1) break;
        __syncthreads();
        if (tid == 0) {
            __threadfence();
            atomicAdd(&g_bar, 1u);
            unsigned target = (unsigned)NB * (unsigned)(t + 1);
            volatile unsigned* vb = (volatile unsigned*)&g_bar;
            while (*vb < target) __nanosleep(64);
            __threadfence();
        }
        __syncthreads();
    }
}

extern "C" void kernel_launch(void* const* d_in, const int* in_sizes, int n_in,
                              void* d_out, int out_size) {
    const float* x     = (const float*)d_in[0];
    const float* wm    = (const float*)d_in[1];
    const float* conn  = (const float*)d_in[2];
    const float* mask  = (const float*)d_in[3];
    const float* W_in  = (const float*)d_in[4];
    const float* W_rec = (const float*)d_in[5];
    const float* bias  = (const float*)d_in[6];
    float* out = (float*)d_out;

    void *hy_ptr, *hz_ptr, *bar_ptr;
    cudaGetSymbolAddress(&hy_ptr,  g_hy);
    cudaGetSymbolAddress(&hz_ptr,  g_hz);
    cudaGetSymbolAddress(&bar_ptr, g_bar);

    // reset recurrent state + barrier (graph-capturable memset nodes)
    cudaMemsetAsync(hy_ptr, 0, sizeof(float)*NROW);   // only buffer 0 needs zeroing
    cudaMemsetAsync(hz_ptr, 0, sizeof(float)*NROW);
    cudaMemsetAsync(bar_ptr, 0, sizeof(unsigned));

    bin_kernel<<<dim3(TT, MM), NTHR>>>(x, mask, W_in, bias);
    step_kernel<<<NB, NTHR>>>(wm, conn, W_rec, out);
}

// round 3
// speedup vs baseline: 1.1806x; 1.1806x over previous
#include <cuda_runtime.h>
#include <cuda_fp16.h>

#define TT 256
#define MM 16
#define HH 256
#define II 128
#define NROW (MM*HH)            // 4096
#define NB 148
#define NTHR 512                // step kernel threads
#define BIN_THR 256             // bin kernel threads (one per h)
#define NWARPS (NB*(NTHR/32))   // 2368

#define DT_ 0.042f
#define GAMMA_ 2.7f
#define EPS_ 4.7f

// ---- persistent scratch (no cudaMalloc allowed) ----
__device__ float    g_B[TT*NROW];     // W_in@u + bias, 4 MB
__device__ float    g_hy[2][NROW];    // double-buffered hy state
__device__ float    g_hz[NROW];
__device__ unsigned g_bar;

// ============================================================
// Precompute B[t, m*H+h] = mask[m]*dot(W_in[m,h,:], x[t,:]) + bias[m,h]
// grid=(T,M), block=BIN_THR=256 (one thread per h)
// ============================================================
__global__ void bin_kernel(const float* __restrict__ x,
                           const float* __restrict__ input_mask,
                           const float* __restrict__ W_in,
                           const float* __restrict__ bias) {
    __shared__ float4 xs[II/4];
    int t = blockIdx.x, m = blockIdx.y, h = threadIdx.x;
    if (h < II/4) xs[h] = ((const float4*)(x + (size_t)t*II))[h];
    __syncthreads();
    const float4* w4 = (const float4*)(W_in + ((size_t)m*HH + h)*II);
    float s = 0.f;
#pragma unroll
    for (int k = 0; k < II/4; ++k) {
        float4 a = w4[k], b = xs[k];
        s += a.x*b.x + a.y*b.y + a.z*b.z + a.w*b.w;
    }
    g_B[((size_t)t*MM + m)*HH + h] = input_mask[m]*s + bias[m*HH + h];
}

// ============================================================
// Persistent recurrent step kernel. One warp per output row (i,h),
// 2 rows/warp critical path at 512 thr/CTA.
// Skips wm blocks where conn[i,o]==0 (~halves weight traffic).
// ============================================================
__global__ void __launch_bounds__(NTHR, 1)
step_kernel(const float* __restrict__ wm,
            const float* __restrict__ conn,
            const float* __restrict__ wrec,
            float* __restrict__ out) {
    __shared__ float hy_sh[NROW];        // 16 KB snapshot of hy
    __shared__ float conn_sh[MM*MM];
    __shared__ float scal_sh[MM];

    int tid  = threadIdx.x;
    int lane = tid & 31;
    int gwarp = blockIdx.x * (NTHR/32) + (tid >> 5);

    if (tid < MM*MM) conn_sh[tid] = conn[tid];
    __syncthreads();
    if (tid < MM) {
        float s = 0.f;
#pragma unroll
        for (int o = 0; o < MM; ++o) s += conn_sh[tid*MM + o];
        scal_sh[tid] = 1.f / fmaxf(s, 1.f);
    }

    float* state_out = out;                       // [T][M][2][H]
    float* fb_out    = out + (size_t)TT*MM*2*HH;  // [T][M][H]

    for (int t = 0; t < TT; ++t) {
        int p = t & 1;
        __syncthreads();   // hy_sh reuse + scal_sh first use
        {
            const float4* src = (const float4*)g_hy[p];
            float4* dst = (float4*)hy_sh;
            for (int k = tid; k < NROW/4; k += NTHR) dst[k] = src[k];
        }
        __syncthreads();

        const float4* hy4 = (const float4*)hy_sh;
        for (int row = gwarp; row < NROW; row += NWARPS) {
            int i = row >> 8, h = row & (HH-1);
            // hoist scalar state loads so they overlap the dot products
            float hzp = 0.f, Bv = 0.f;
            if (lane == 0) { hzp = g_hz[row]; Bv = g_B[(size_t)t*NROW + row]; }

            // ---- feedback over nonzero conn blocks ----
            float fb = 0.f;
            const float* wmrow = wm + (((size_t)i*MM)*HH + h)*HH;  // wm[i][0][h][0]
#pragma unroll
            for (int o = 0; o < MM; ++o) {
                if (conn_sh[i*MM + o] != 0.f) {
                    const float4* w4 = (const float4*)(wmrow + (size_t)o*HH*HH);
                    const float4* b4 = hy4 + o*(HH/4);
                    float4 a = w4[lane],    b = b4[lane];
                    fb += a.x*b.x + a.y*b.y + a.z*b.z + a.w*b.w;
                    a = w4[lane+32]; b = b4[lane+32];
                    fb += a.x*b.x + a.y*b.y + a.z*b.z + a.w*b.w;
                }
            }
            // ---- block-diagonal recurrent term ----
            float rec = 0.f;
            {
                const float4* w4 = (const float4*)(wrec + ((size_t)i*HH + h)*HH);
                const float4* b4 = hy4 + i*(HH/4);
                float4 a = w4[lane],    b = b4[lane];
                rec += a.x*b.x + a.y*b.y + a.z*b.z + a.w*b.w;
                a = w4[lane+32]; b = b4[lane+32];
                rec += a.x*b.x + a.y*b.y + a.z*b.z + a.w*b.w;
            }
#pragma unroll
            for (int off = 16; off; off >>= 1) {
                fb  += __shfl_xor_sync(0xffffffffu, fb,  off);
                rec += __shfl_xor_sync(0xffffffffu, rec, off);
            }
            if (lane == 0) {
                fb *= scal_sh[i];
                float hyp = hy_sh[row];
                float pre = fb + rec + Bv;
                float hzn = hzp + DT_ * (tanhf(pre) - GAMMA_*hyp - EPS_*hzp);
                float hyn = hyp + DT_ * hzn;
                g_hz[row]      = hzn;
                g_hy[1-p][row] = hyn;
                size_t sb = ((size_t)(t*MM + i)*2)*HH;
                state_out[sb + h]      = hyn;
                state_out[sb + HH + h] = hzn;
                fb_out[(size_t)(t*MM + i)*HH + h] = fb;
            }
        }

        // ---- grid barrier (monotonic counter) ----
        if (t == TT-1) break;
        __syncthreads();
        if (tid == 0) {
            __threadfence();
            atomicAdd(&g_bar, 1u);
            unsigned target = (unsigned)NB * (unsigned)(t + 1);
            volatile unsigned* vb = (volatile unsigned*)&g_bar;
            while (*vb < target) __nanosleep(64);
            __threadfence();
        }
        __syncthreads();
    }
}

extern "C" void kernel_launch(void* const* d_in, const int* in_sizes, int n_in,
                              void* d_out, int out_size) {
    const float* x     = (const float*)d_in[0];
    const float* wm    = (const float*)d_in[1];
    const float* conn  = (const float*)d_in[2];
    const float* mask  = (const float*)d_in[3];
    const float* W_in  = (const float*)d_in[4];
    const float* W_rec = (const float*)d_in[5];
    const float* bias  = (const float*)d_in[6];
    float* out = (float*)d_out;

    void *hy_ptr, *hz_ptr, *bar_ptr;
    cudaGetSymbolAddress(&hy_ptr,  g_hy);
    cudaGetSymbolAddress(&hz_ptr,  g_hz);
    cudaGetSymbolAddress(&bar_ptr, g_bar);

    cudaMemsetAsync(hy_ptr, 0, sizeof(float)*NROW);
    cudaMemsetAsync(hz_ptr, 0, sizeof(float)*NROW);
    cudaMemsetAsync(bar_ptr, 0, sizeof(unsigned));

    bin_kernel<<<dim3(TT, MM), BIN_THR>>>(x, mask, W_in, bias);
    step_kernel<<<NB, NTHR>>>(wm, conn, W_rec, out);
}

// round 4
// speedup vs baseline: 1.2316x; 1.0432x over previous
#include <cuda_runtime.h>

#define TT 256
#define MM 16
#define HH 256
#define II 128
#define NROW (MM*HH)          // 4096
#define NB 128                // CTAs: 128*32 warps = 4096 = one warp per row
#define NTHR 1024
#define BIN_THR 256

#define DT_ 0.042f
#define GAMMA_ 2.7f
#define EPS_ 4.7f

// ---- persistent scratch (no cudaMalloc allowed) ----
__device__ float    g_B[TT*NROW];     // W_in@u + bias, 4 MB
__device__ float    g_hy[2][NROW];    // double-buffered published hy
__device__ unsigned g_bar;

// ============================================================
// Precompute B[t, m*H+h] = mask[m]*dot(W_in[m,h,:], x[t,:]) + bias[m,h]
// ============================================================
__global__ void bin_kernel(const float* __restrict__ x,
                           const float* __restrict__ input_mask,
                           const float* __restrict__ W_in,
                           const float* __restrict__ bias) {
    __shared__ float4 xs[II/4];
    int t = blockIdx.x, m = blockIdx.y, h = threadIdx.x;
    if (h < II/4) xs[h] = ((const float4*)(x + (size_t)t*II))[h];
    __syncthreads();
    const float4* w4 = (const float4*)(W_in + ((size_t)m*HH + h)*II);
    float s = 0.f;
#pragma unroll
    for (int k = 0; k < II/4; ++k) {
        float4 a = w4[k], b = xs[k];
        s += a.x*b.x + a.y*b.y + a.z*b.z + a.w*b.w;
    }
    g_B[((size_t)t*MM + m)*HH + h] = input_mask[m]*s + bias[m*HH + h];
}

// ============================================================
// Persistent step kernel: one warp permanently owns one row (i,h).
// hz / own-hy / base pointers are register-resident for all 256 steps.
// ============================================================
__global__ void __launch_bounds__(NTHR, 1)
step_kernel(const float* __restrict__ wm,
            const float* __restrict__ conn,
            const float* __restrict__ wrec,
            float* __restrict__ out) {
    __shared__ float hy_sh[NROW];        // 16 KB snapshot
    __shared__ int   list_sh[MM][MM];    // nonzero conn block indices per module
    __shared__ int   cnt_sh[MM];
    __shared__ float scal_sh[MM];

    int tid  = threadIdx.x;
    int lane = tid & 31;
    int wid  = tid >> 5;
    int row  = blockIdx.x * 32 + wid;    // 0..4095, fixed forever
    int i = row >> 8, h = row & (HH-1);

    if (tid < MM) {
        int c = 0; float s = 0.f;
#pragma unroll
        for (int o = 0; o < MM; ++o) {
            float v = conn[tid*MM + o];
            s += v;
            if (v != 0.f) list_sh[tid][c++] = o;
        }
        cnt_sh[tid]  = c;
        scal_sh[tid] = 1.f / fmaxf(s, 1.f);
    }
    __syncthreads();

    const int   cnt  = cnt_sh[i];
    const float scal = scal_sh[i];
    const float* wmbase = wm + ((size_t)i*MM*HH + h)*HH;   // wm[i][0][h][0]
    const float4* wr4   = (const float4*)(wrec + ((size_t)i*HH + h)*HH);

    float hyp = 0.f, hzp = 0.f;          // register-resident state

    float* state_out = out;                       // [T][M][2][H]
    float* fb_out    = out + (size_t)TT*MM*2*HH;  // [T][M][H]

    for (int t = 0; t < TT; ++t) {
        int p = t & 1;
        // snapshot published hy (1024 float4 over 1024 threads)
        ((float4*)hy_sh)[tid] = ((const float4*)g_hy[p])[tid];
        __syncthreads();

        float Bv = g_B[(size_t)t*NROW + row];    // warp-uniform broadcast

        const float4* hy4 = (const float4*)hy_sh;
        float fb0 = 0.f, fb1 = 0.f;
        int k = 0;
        for (; k + 2 <= cnt; k += 2) {
            int o0 = list_sh[i][k], o1 = list_sh[i][k+1];
            const float4* w0 = (const float4*)(wmbase + (size_t)o0*HH*HH);
            const float4* w1 = (const float4*)(wmbase + (size_t)o1*HH*HH);
            float4 a0 = w0[lane], a1 = w0[lane+32];
            float4 a2 = w1[lane], a3 = w1[lane+32];
            float4 b0 = hy4[o0*64 + lane],  b1 = hy4[o0*64 + 32 + lane];
            float4 b2 = hy4[o1*64 + lane],  b3 = hy4[o1*64 + 32 + lane];
            fb0 += a0.x*b0.x + a0.y*b0.y + a0.z*b0.z + a0.w*b0.w
                 + a1.x*b1.x + a1.y*b1.y + a1.z*b1.z + a1.w*b1.w;
            fb1 += a2.x*b2.x + a2.y*b2.y + a2.z*b2.z + a2.w*b2.w
                 + a3.x*b3.x + a3.y*b3.y + a3.z*b3.z + a3.w*b3.w;
        }
        if (k < cnt) {
            int o0 = list_sh[i][k];
            const float4* w0 = (const float4*)(wmbase + (size_t)o0*HH*HH);
            float4 a0 = w0[lane], a1 = w0[lane+32];
            float4 b0 = hy4[o0*64 + lane], b1 = hy4[o0*64 + 32 + lane];
            fb0 += a0.x*b0.x + a0.y*b0.y + a0.z*b0.z + a0.w*b0.w
                 + a1.x*b1.x + a1.y*b1.y + a1.z*b1.z + a1.w*b1.w;
        }
        float rec;
        {
            float4 a0 = wr4[lane], a1 = wr4[lane+32];
            float4 b0 = hy4[i*64 + lane], b1 = hy4[i*64 + 32 + lane];
            rec = a0.x*b0.x + a0.y*b0.y + a0.z*b0.z + a0.w*b0.w
                + a1.x*b1.x + a1.y*b1.y + a1.z*b1.z + a1.w*b1.w;
        }
        float fb = fb0 + fb1;
#pragma unroll
        for (int off = 16; off; off >>= 1) {
            fb  += __shfl_xor_sync(0xffffffffu, fb,  off);
            rec += __shfl_xor_sync(0xffffffffu, rec, off);
        }
        fb *= scal;
        float pre = fb + rec + Bv;
        float hzn = hzp + DT_ * (tanhf(pre) - GAMMA_*hyp - EPS_*hzp);
        float hyn = hyp + DT_ * hzn;
        hzp = hzn; hyp = hyn;

        if (lane == 0) {
            size_t sb = ((size_t)(t*MM + i)*2)*HH;
            state_out[sb + h]      = hyn;
            state_out[sb + HH + h] = hzn;
            fb_out[(size_t)(t*MM + i)*HH + h] = fb;
            g_hy[1-p][row] = hyn;            // publish for next step
        }

        if (t == TT-1) break;
        __syncthreads();
        if (tid == 0) {
            __threadfence();
            atomicAdd(&g_bar, 1u);
            unsigned target = (unsigned)NB * (unsigned)(t + 1);
            volatile unsigned* vb = (volatile unsigned*)&g_bar;
            while (*vb < target) __nanosleep(32);
            __threadfence();
        }
        __syncthreads();
    }
}

extern "C" void kernel_launch(void* const* d_in, const int* in_sizes, int n_in,
                              void* d_out, int out_size) {
    const float* x     = (const float*)d_in[0];
    const float* wm    = (const float*)d_in[1];
    const float* conn  = (const float*)d_in[2];
    const float* mask  = (const float*)d_in[3];
    const float* W_in  = (const float*)d_in[4];
    const float* W_rec = (const float*)d_in[5];
    const float* bias  = (const float*)d_in[6];
    float* out = (float*)d_out;

    void *hy_ptr, *bar_ptr;
    cudaGetSymbolAddress(&hy_ptr,  g_hy);
    cudaGetSymbolAddress(&bar_ptr, g_bar);

    cudaMemsetAsync(hy_ptr, 0, sizeof(float)*NROW);   // zero buffer 0 only
    cudaMemsetAsync(bar_ptr, 0, sizeof(unsigned));

    bin_kernel<<<dim3(TT, MM), BIN_THR>>>(x, mask, W_in, bias);
    step_kernel<<<NB, NTHR>>>(wm, conn, W_rec, out);
}